// round 15
// baseline (speedup 1.0000x reference)
#include <cuda_runtime.h>

// 2 samples per CTA, sequential dense GEMV1s + ONE MERGED sparse GEMV2.
//   h = relu(x[b,:] @ w1[b,:,:] + b1[b,:])   (D=128 -> H=256)
//   out = h @ w2[b,:,:] + b2[b,:]            (H=256 -> C=64)
// w2 rows with h[j]==0 are never loaded (exact, ~50% skipped).
// Why merge: with one sample, ~half the predicated LDGs are off -> the
// sparse phase's in-flight load count (and DRAM demand) halves (measured
// 5.3 TB/s vs 6.8 dense). Merging two samples' sparse loops offers 2
// independent predicated loads per iteration (expected 1 active) ->
// demand restored to dense levels with no dense/sparse instruction fusion.
// Grid 2048 x 128 thr, lb(128,10): R13's proven occupancy point.

#define B_DIM 4096
#define D_DIM 128
#define H_DIM 256
#define C_DIM 64

__global__ void __launch_bounds__(128, 10) mlp_merge2_kernel(
    const float* __restrict__ x,
    const float* __restrict__ w1,
    const float* __restrict__ b1,
    const float* __restrict__ w2,
    const float* __restrict__ b2,
    float* __restrict__ out)
{
    const int l  = threadIdx.x;            // 0..127
    const int b0 = blockIdx.x * 2;         // sample A; B = b0+1

    __shared__ float  x_s[2][D_DIM];       // 1 KB
    __shared__ float  h_s[2][H_DIM];       // 2 KB
    __shared__ float4 part_a[128];         // 2 KB
    __shared__ float4 part_b[128];         // 2 KB

    // ---- stage both x vectors (contiguous 1KB, 128 lanes x float2) ----
    reinterpret_cast<float2*>(&x_s[0][0])[l] =
        reinterpret_cast<const float2*>(x + (size_t)b0 * D_DIM)[l];
    __syncthreads();

    const int g     = l & 63;              // GEMV1 column group
    const int dbase = (l >> 6) * 64;       // GEMV1 d-range

    // ======== GEMV1 for A then B: proven dense loop, run twice ============
    #pragma unroll 1
    for (int k = 0; k < 2; ++k) {
        const int bk = b0 + k;
        const float4* w1v = reinterpret_cast<const float4*>(
            w1 + (size_t)bk * D_DIM * H_DIM);

        float4 acc = make_float4(0.f, 0.f, 0.f, 0.f);
        #pragma unroll
        for (int i = 0; i < 64; ++i) {
            const int d = dbase + i;
            const float  xv = x_s[k][d];
            const float4 w  = __ldcs(&w1v[d * (H_DIM / 4) + g]);
            acc.x = fmaf(xv, w.x, acc.x);
            acc.y = fmaf(xv, w.y, acc.y);
            acc.z = fmaf(xv, w.z, acc.z);
            acc.w = fmaf(xv, w.w, acc.w);
        }
        part_a[l] = acc;
        __syncthreads();

        if (l < 64) {
            float4 s0 = part_a[l];
            float4 s1 = part_a[64 + l];
            float4 bb = reinterpret_cast<const float4*>(
                b1 + (size_t)bk * H_DIM)[l];
            float4 h4;
            h4.x = fmaxf(s0.x + s1.x + bb.x, 0.f);
            h4.y = fmaxf(s0.y + s1.y + bb.y, 0.f);
            h4.z = fmaxf(s0.z + s1.z + bb.z, 0.f);
            h4.w = fmaxf(s0.w + s1.w + bb.w, 0.f);
            reinterpret_cast<float4*>(h_s[k])[l] = h4;
        }
        __syncthreads();
    }

    // ======== merged sparse GEMV2 for A and B ==============================
    // w2[b] as float4[256][16]. Thread: (jslot = l>>4 in 0..7, cg = l&15).
    // Row j = jslot + 8*i (affine). Register masks decouple predicates from
    // the load loop; 2 independent predicated streams keep in-flight loads
    // at dense-phase levels.
    {
        const int cg    = l & 15;
        const int jslot = l >> 4;
        const float4* w2a = reinterpret_cast<const float4*>(
            w2 + (size_t)b0 * H_DIM * C_DIM);
        const float4* w2b = reinterpret_cast<const float4*>(
            w2 + (size_t)(b0 + 1) * H_DIM * C_DIM);

        unsigned mA = 0, mB = 0;
        #pragma unroll
        for (int i = 0; i < 32; ++i) {
            const int j = jslot + i * 8;
            mA |= (h_s[0][j] > 0.f) ? (1u << i) : 0u;
            mB |= (h_s[1][j] > 0.f) ? (1u << i) : 0u;
        }

        float4 accA = make_float4(0.f, 0.f, 0.f, 0.f);
        float4 accB = make_float4(0.f, 0.f, 0.f, 0.f);
        #pragma unroll 8
        for (int i = 0; i < 32; ++i) {
            const int j = jslot + i * 8;
            if ((mA >> i) & 1u) {
                const float4 wv = __ldcs(&w2a[j * (C_DIM / 4) + cg]);
                const float  hv = h_s[0][j];
                accA.x = fmaf(hv, wv.x, accA.x);
                accA.y = fmaf(hv, wv.y, accA.y);
                accA.z = fmaf(hv, wv.z, accA.z);
                accA.w = fmaf(hv, wv.w, accA.w);
            }
            if ((mB >> i) & 1u) {
                const float4 wv = __ldcs(&w2b[j * (C_DIM / 4) + cg]);
                const float  hv = h_s[1][j];
                accB.x = fmaf(hv, wv.x, accB.x);
                accB.y = fmaf(hv, wv.y, accB.y);
                accB.z = fmaf(hv, wv.z, accB.z);
                accB.w = fmaf(hv, wv.w, accB.w);
            }
        }
        part_a[l] = accA;
        part_b[l] = accB;
    }
    __syncthreads();

    // ======== final reduces: lanes 0-15 -> out(A), 16-31 -> out(B) =========
    if (l < 16) {
        float4 acc = part_a[l];
        #pragma unroll
        for (int k = 1; k < 8; ++k) {
            float4 p = part_a[k * 16 + l];
            acc.x += p.x; acc.y += p.y; acc.z += p.z; acc.w += p.w;
        }
        float4 bb = reinterpret_cast<const float4*>(b2 + (size_t)b0 * C_DIM)[l];
        acc.x += bb.x; acc.y += bb.y; acc.z += bb.z; acc.w += bb.w;
        __stcs(reinterpret_cast<float4*>(out + (size_t)b0 * C_DIM) + l, acc);
    } else if (l < 32) {
        const int t = l - 16;
        float4 acc = part_b[t];
        #pragma unroll
        for (int k = 1; k < 8; ++k) {
            float4 p = part_b[k * 16 + t];
            acc.x += p.x; acc.y += p.y; acc.z += p.z; acc.w += p.w;
        }
        float4 bb = reinterpret_cast<const float4*>(
            b2 + (size_t)(b0 + 1) * C_DIM)[t];
        acc.x += bb.x; acc.y += bb.y; acc.z += bb.z; acc.w += bb.w;
        __stcs(reinterpret_cast<float4*>(
            out + (size_t)(b0 + 1) * C_DIM) + t, acc);
    }
}

extern "C" void kernel_launch(void* const* d_in, const int* in_sizes, int n_in,
                              void* d_out, int out_size)
{
    const float* x  = (const float*)d_in[0];
    const float* w1 = (const float*)d_in[1];
    const float* b1 = (const float*)d_in[2];
    const float* w2 = (const float*)d_in[3];
    const float* b2 = (const float*)d_in[4];
    float* out = (float*)d_out;

    mlp_merge2_kernel<<<B_DIM / 2, 128>>>(x, w1, b1, w2, b2, out);
}